// round 2
// baseline (speedup 1.0000x reference)
#include <cuda_runtime.h>

// ManeuverHead: segmented-rank slot assignment + fused 2-layer MLP head.
// Shapes (fixed by problem): N=262144 nodes, B=4096 graphs, D=128, G=8, R=7.
//
// Pipeline:
//   k_init     : zero per-batch counters, slotNode = -1
//   k_count    : per-block masked-node sums + per-batch counts (atomics)
//   k_scan     : exclusive scans of block sums (256) and batch counts (4096)
//   k_scatter  : exact in-order within-batch rank -> slotNode[b*8+rank] = node
//   k_gpart    : gpart[b][k] = global[b] @ w1[128:256] + b1   (4096x128x128)
//   k_main     : per-slot gathered GEMM  h = relu(F @ w1[0:128] + gpart),
//                scores = h @ w2 + b2, masked writes (occ & maneuver mask)
// GEMMs use packed fp32 FMA (fma.rn.f32x2) with 8x8 register tiles.

#define NNODES   262144
#define NB       4096
#define DD       128
#define GG       8
#define RR       7
#define NSLOTS   (NB * GG)          // 32768
#define NEGV     (-1e9f)

typedef unsigned long long ull_t;

// ---------------- device scratch (static: no allocations allowed) ---------
__device__ int   d_blockSums[256];
__device__ int   d_blockOff[256];
__device__ int   d_counts[NB];
__device__ int   d_cbase[NB];
__device__ int   d_slotNode[NSLOTS];
__device__ float d_gpart[NB * DD];

// ---------------- packed fp32x2 helpers ----------------------------------
__device__ __forceinline__ ull_t pack2(float x, float y) {
    ull_t r;
    asm("mov.b64 %0, {%1, %2};" : "=l"(r) : "f"(x), "f"(y));
    return r;
}
__device__ __forceinline__ ull_t fma2(ull_t a, ull_t b, ull_t c) {
    ull_t d;
    asm("fma.rn.f32x2 %0, %1, %2, %3;" : "=l"(d) : "l"(a), "l"(b), "l"(c));
    return d;
}
__device__ __forceinline__ float2 unpack2(ull_t v) {
    float2 f;
    asm("mov.b64 {%0, %1}, %2;" : "=f"(f.x), "=f"(f.y) : "l"(v));
    return f;
}

// ---------------- K0: init ------------------------------------------------
__global__ void k_init() {
    int i = blockIdx.x * 256 + threadIdx.x;
    if (i < NSLOTS) d_slotNode[i] = -1;
    if (i < NB)     d_counts[i]   = 0;
}

// ---------------- K1: block sums + per-batch counts -----------------------
__global__ void k_count(const int* __restrict__ mask, const int* __restrict__ batch) {
    __shared__ int sh[256];
    int t = threadIdx.x;
    int base = (blockIdx.x * 256 + t) * 4;
    int s = 0;
#pragma unroll
    for (int j = 0; j < 4; j++) {
        if (mask[base + j] != 0) {
            s++;
            atomicAdd(&d_counts[batch[base + j]], 1);
        }
    }
    sh[t] = s;
    __syncthreads();
    for (int off = 128; off > 0; off >>= 1) {
        if (t < off) sh[t] += sh[t + off];
        __syncthreads();
    }
    if (t == 0) d_blockSums[blockIdx.x] = sh[0];
}

// ---------------- K2: scans (one block, 1024 threads) ----------------------
__global__ void k_scan() {
    __shared__ int sh[1024];
    int t = threadIdx.x;

    // scan counts[4096] -> cbase (exclusive)
    int c[4];
    int s = 0;
#pragma unroll
    for (int j = 0; j < 4; j++) { c[j] = d_counts[4 * t + j]; s += c[j]; }
    sh[t] = s;
    __syncthreads();
    for (int off = 1; off < 1024; off <<= 1) {
        int x = (t >= off) ? sh[t - off] : 0;
        __syncthreads();
        sh[t] += x;
        __syncthreads();
    }
    int excl = sh[t] - s;
#pragma unroll
    for (int j = 0; j < 4; j++) { d_cbase[4 * t + j] = excl; excl += c[j]; }
    __syncthreads();

    // scan blockSums[256] -> blockOff (exclusive)
    int v = (t < 256) ? d_blockSums[t] : 0;
    sh[t] = v;
    __syncthreads();
    for (int off = 1; off < 1024; off <<= 1) {
        int x = (t >= off) ? sh[t - off] : 0;
        __syncthreads();
        sh[t] += x;
        __syncthreads();
    }
    if (t < 256) d_blockOff[t] = sh[t] - v;
}

// ---------------- K3: in-order rank + slot scatter -------------------------
__global__ void k_scatter(const int* __restrict__ mask, const int* __restrict__ batch) {
    __shared__ int sh[256];
    int t = threadIdx.x;
    int base = (blockIdx.x * 256 + t) * 4;
    int g[4];
    int s = 0;
#pragma unroll
    for (int j = 0; j < 4; j++) { g[j] = (mask[base + j] != 0); s += g[j]; }
    sh[t] = s;
    __syncthreads();
    for (int off = 1; off < 256; off <<= 1) {
        int x = (t >= off) ? sh[t - off] : 0;
        __syncthreads();
        sh[t] += x;
        __syncthreads();
    }
    // global count of masked nodes strictly before this thread's first element
    int pre = d_blockOff[blockIdx.x] + sh[t] - s;
#pragma unroll
    for (int j = 0; j < 4; j++) {
        if (g[j]) {
            int b = batch[base + j];
            int rank = pre - d_cbase[b];    // within-batch rank (batch sorted)
            if (rank < GG) d_slotNode[b * GG + rank] = base + j;
            pre++;
        }
    }
}

// ---------------- shared GEMM inner loop ----------------------------------
// Fp: rows of A in shared, leading dim 132.  Wp: [k][n] in shared, ld 128.
// acc[MR][4] packed f32x2 pairs covering 8 n-columns (thread's tx*8 .. +7).
template <int MR>
__device__ __forceinline__ void mma_loop(const float* __restrict__ Fp,
                                         const float* __restrict__ Wp,
                                         ull_t acc[MR][4]) {
#pragma unroll 1
    for (int k = 0; k < 128; k += 4) {
        float4 fa[MR];
#pragma unroll
        for (int i = 0; i < MR; i++)
            fa[i] = *(const float4*)(Fp + i * 132 + k);
        ull_t wv[4][4];
#pragma unroll
        for (int kk = 0; kk < 4; kk++) {
            const float* wr = Wp + (k + kk) * 128;
#pragma unroll
            for (int jj = 0; jj < 4; jj++)
                wv[kk][jj] = *(const ull_t*)(wr + jj * 2);
        }
#pragma unroll
        for (int kk = 0; kk < 4; kk++) {
#pragma unroll
            for (int i = 0; i < MR; i++) {
                float f = kk == 0 ? fa[i].x : kk == 1 ? fa[i].y
                        : kk == 2 ? fa[i].z : fa[i].w;
                ull_t fp = pack2(f, f);
#pragma unroll
                for (int jj = 0; jj < 4; jj++)
                    acc[i][jj] = fma2(fp, wv[kk][jj], acc[i][jj]);
            }
        }
    }
}

// ---------------- K4: gpart = global @ w1[128:] + b1 -----------------------
// grid 128 blocks x 32 rows, 256 threads (tx=n-group of 8, ty=row-pair)
#define GP_SMEM_BYTES ((32 * 132 + 128 * 128 + 128) * 4)
__global__ void k_gpart(const float* __restrict__ gf,
                        const float* __restrict__ w1,
                        const float* __restrict__ b1) {
    extern __shared__ float smem[];
    float* A_s  = smem;                 // [32][132]
    float* W_s  = smem + 32 * 132;      // [128][128]
    float* b1_s = W_s + 128 * 128;      // [128]

    int t  = threadIdx.x;
    int tx = t & 15, ty = t >> 4;
    int row0 = blockIdx.x * 32;

    {   // stage w1 rows 128..255 (global-feature half)
        const float4* src = (const float4*)(w1 + 128 * 128);
        float4* dst = (float4*)W_s;
        for (int i = t; i < 4096; i += 256) dst[i] = src[i];
    }
    for (int i = t; i < 1024; i += 256) {   // 32 rows x 32 float4
        int r = i >> 5, c = i & 31;
        *(float4*)&A_s[r * 132 + c * 4] = ((const float4*)gf)[(row0 + r) * 32 + c];
    }
    if (t < 128) b1_s[t] = b1[t];
    __syncthreads();

    ull_t acc[2][4];
#pragma unroll
    for (int i = 0; i < 2; i++)
#pragma unroll
        for (int j = 0; j < 4; j++) acc[i][j] = 0ull;

    mma_loop<2>(A_s + (ty * 2) * 132, W_s + tx * 8, acc);

#pragma unroll
    for (int i = 0; i < 2; i++) {
        int row = row0 + ty * 2 + i;
#pragma unroll
        for (int jj = 0; jj < 4; jj++) {
            int n = tx * 8 + jj * 2;
            float2 a = unpack2(acc[i][jj]);
            a.x += b1_s[n];
            a.y += b1_s[n + 1];
            *(float2*)&d_gpart[row * 128 + n] = a;
        }
    }
}

// ---------------- K5: main gathered GEMM + head ----------------------------
// grid 256 blocks x 128 slots, 256 threads (tx in [0,16) -> 8 n-cols,
// ty in [0,16) -> 8 slot-rows). All 8 rows of a thread share one batch b.
#define MAIN_SMEM_FLOATS (128 * 132 + 128 * 128 + 16 * 128 + 128 * 7 + 8)
#define MAIN_SMEM_BYTES  (MAIN_SMEM_FLOATS * 4 + 128 * 4)
__global__ void k_main(const float* __restrict__ nf,
                       const float* __restrict__ w1,
                       const float* __restrict__ w2,
                       const float* __restrict__ b2,
                       const int* __restrict__ mvm,
                       float* __restrict__ out) {
    extern __shared__ float smem[];
    float* F_s  = smem;                         // [128][132]
    float* W_s  = smem + 128 * 132;             // [128][128]
    float* gp_s = W_s + 128 * 128;              // [16][128]
    float* w2_s = gp_s + 16 * 128;              // [128*7]
    float* b2_s = w2_s + 128 * 7;               // [7] (pad 8)
    int*   node_s = (int*)(b2_s + 8);           // [128]

    int t  = threadIdx.x;
    int tx = t & 15, ty = t >> 4;
    int slot0 = blockIdx.x * 128;
    int b0    = blockIdx.x * 16;

    if (t < 128) node_s[t] = d_slotNode[slot0 + t];
    for (int i = t; i < 128 * 7; i += 256) w2_s[i] = w2[i];
    if (t < 7) b2_s[t] = b2[t];
    {   // w1 rows 0..127 (node-feature half)
        const float4* src = (const float4*)w1;
        float4* dst = (float4*)W_s;
        for (int i = t; i < 4096; i += 256) dst[i] = src[i];
    }
    {   // gpart rows for this block's 16 batches
        const float4* src = (const float4*)d_gpart + b0 * 32;
        float4* dst = (float4*)gp_s;
        for (int i = t; i < 512; i += 256) dst[i] = src[i];
    }
    __syncthreads();   // node_s ready before gather

    {   // gather node rows (zeros for empty slots)
        const float4 z = make_float4(0.f, 0.f, 0.f, 0.f);
        for (int i = t; i < 4096; i += 256) {
            int row = i >> 5, c = i & 31;
            int nd = node_s[row];
            float4 v = (nd >= 0) ? ((const float4*)nf)[nd * 32 + c] : z;
            *(float4*)&F_s[row * 132 + c * 4] = v;
        }
    }
    __syncthreads();

    ull_t acc[8][4];
#pragma unroll
    for (int i = 0; i < 8; i++)
#pragma unroll
        for (int j = 0; j < 4; j++) acc[i][j] = 0ull;

    mma_loop<8>(F_s + (ty * 8) * 132, W_s + tx * 8, acc);

    // ---- epilogue: relu + second layer, reduced across the 16 tx lanes ----
    float gpv[8];
#pragma unroll
    for (int j = 0; j < 8; j++) gpv[j] = gp_s[ty * 128 + tx * 8 + j];

    float w2v[8][RR];
#pragma unroll
    for (int j = 0; j < 8; j++)
#pragma unroll
        for (int r = 0; r < RR; r++)
            w2v[j][r] = w2_s[(tx * 8 + j) * RR + r];

    float sc[8][RR];
#pragma unroll
    for (int i = 0; i < 8; i++) {
        float h[8];
#pragma unroll
        for (int jj = 0; jj < 4; jj++) {
            float2 a = unpack2(acc[i][jj]);
            h[2 * jj]     = fmaxf(a.x + gpv[2 * jj], 0.f);
            h[2 * jj + 1] = fmaxf(a.y + gpv[2 * jj + 1], 0.f);
        }
#pragma unroll
        for (int r = 0; r < RR; r++) {
            float s = 0.f;
#pragma unroll
            for (int j = 0; j < 8; j++) s = fmaf(h[j], w2v[j][r], s);
            sc[i][r] = s;
        }
    }
    // butterfly-reduce partial dots across the 16 tx lanes of this ty group
#pragma unroll
    for (int i = 0; i < 8; i++)
#pragma unroll
        for (int r = 0; r < RR; r++) {
            float v = sc[i][r];
            v += __shfl_xor_sync(0xffffffffu, v, 8);
            v += __shfl_xor_sync(0xffffffffu, v, 4);
            v += __shfl_xor_sync(0xffffffffu, v, 2);
            v += __shfl_xor_sync(0xffffffffu, v, 1);
            sc[i][r] = v;
        }

    // ---- masked writes: slot = slot0 + ty*8 + i  ->  b = b0+ty, g = i ----
    int orow = (b0 + ty) * (GG * RR);
#pragma unroll
    for (int i = 0; i < 8; i++) {
        int occ = node_s[ty * 8 + i] >= 0;
#pragma unroll
        for (int r = 0; r < RR; r++) {
            int col = i * RR + r;
            if ((col & 15) == tx) {     // exactly one lane per output
                float v = NEGV;
                if (occ && mvm[orow + col] != 0) v = sc[i][r] + b2_s[r];
                out[orow + col] = v;
            }
        }
    }
}

// ---------------- launch ---------------------------------------------------
extern "C" void kernel_launch(void* const* d_in, const int* in_sizes, int n_in,
                              void* d_out, int out_size) {
    const float* nf    = (const float*)d_in[0];   // [262144,128]
    const float* gf    = (const float*)d_in[1];   // [4096,128]
    const int*   gmask = (const int*)d_in[2];     // [262144] bool->word
    const int*   mvm   = (const int*)d_in[3];     // [4096,56] bool->word
    const int*   batch = (const int*)d_in[4];     // [262144]
    const float* w1    = (const float*)d_in[5];   // [256,128]
    const float* b1    = (const float*)d_in[6];   // [128]
    const float* w2    = (const float*)d_in[7];   // [128,7]
    const float* b2    = (const float*)d_in[8];   // [7]
    float*       out   = (float*)d_out;           // [4096,56]

    cudaFuncSetAttribute(k_gpart, cudaFuncAttributeMaxDynamicSharedMemorySize,
                         GP_SMEM_BYTES);
    cudaFuncSetAttribute(k_main, cudaFuncAttributeMaxDynamicSharedMemorySize,
                         MAIN_SMEM_BYTES);

    k_init<<<128, 256>>>();
    k_count<<<256, 256>>>(gmask, batch);
    k_scan<<<1, 1024>>>();
    k_scatter<<<256, 256>>>(gmask, batch);
    k_gpart<<<128, 256, GP_SMEM_BYTES>>>(gf, w1, b1);
    k_main<<<256, 256, MAIN_SMEM_BYTES>>>(nf, w1, w2, b2, mvm, out);
}

// round 4
// speedup vs baseline: 1.6152x; 1.6152x over previous
#include <cuda_runtime.h>
#include <cuda_bf16.h>
#include <mma.h>
#include <cstdint>

// ManeuverHead on GB300 (compiled via compute_103 -> WMMA/HMMA path, no tcgen05).
// N=262144 nodes, B=4096, D=128, G=8, R=7.

#define NNODES   262144
#define NB       4096
#define GG       8
#define RR       7
#define NSLOTS   (NB * GG)
#define NEGV     (-1e9f)

using namespace nvcuda;
typedef unsigned long long ull_t;

// ---------------- device scratch ------------------------------------------
__device__ int            d_blockSums[256];
__device__ int            d_blockOff[256];
__device__ int            d_counts[NB];
__device__ int            d_cbase[NB];
__device__ int            d_slotNode[NSLOTS];
__device__ float          d_gpart[NB * 128];
__device__ __nv_bfloat16  d_w1bf[16384];   // w1[0:128][0:128] as bf16 (k-major, row-major)
__device__ __nv_bfloat16  d_w2b[2048];     // w2 padded to [128][16] bf16 (cols 7..15 = 0)

// ---------------- packed fp32x2 helpers (k_gpart) -------------------------
__device__ __forceinline__ ull_t pack2(float x, float y) {
    ull_t r; asm("mov.b64 %0, {%1, %2};" : "=l"(r) : "f"(x), "f"(y)); return r;
}
__device__ __forceinline__ ull_t fma2(ull_t a, ull_t b, ull_t c) {
    ull_t d; asm("fma.rn.f32x2 %0, %1, %2, %3;" : "=l"(d) : "l"(a), "l"(b), "l"(c)); return d;
}
__device__ __forceinline__ float2 unpack2(ull_t v) {
    float2 f; asm("mov.b64 {%0, %1}, %2;" : "=f"(f.x), "=f"(f.y) : "l"(v)); return f;
}

// ---------------- K0: init + bf16 weight staging ---------------------------
__global__ void k_init(const float* __restrict__ w1, const float* __restrict__ w2) {
    int i = blockIdx.x * 256 + threadIdx.x;        // 128 blocks -> 32768 ids
    if (i < NSLOTS) d_slotNode[i] = -1;
    if (i < NB)     d_counts[i]   = 0;
    if (i < 16384)  d_w1bf[i] = __float2bfloat16(w1[i]);   // node half [k][n]
    if (i < 2048) {
        int j = i >> 4, r = i & 15;
        d_w2b[i] = __float2bfloat16(r < RR ? w2[j * RR + r] : 0.f);
    }
}

// ---------------- K1: per-block sums + per-batch counts --------------------
__global__ void k_count(const int* __restrict__ mask, const int* __restrict__ batch) {
    int t = threadIdx.x;
    int gid = blockIdx.x * 256 + t;
    int4 m = ((const int4*)mask)[gid];
    int4 b = ((const int4*)batch)[gid];
    int s = 0;
    if (m.x != 0) { atomicAdd(&d_counts[b.x], 1); s++; }
    if (m.y != 0) { atomicAdd(&d_counts[b.y], 1); s++; }
    if (m.z != 0) { atomicAdd(&d_counts[b.z], 1); s++; }
    if (m.w != 0) { atomicAdd(&d_counts[b.w], 1); s++; }
#pragma unroll
    for (int o = 16; o > 0; o >>= 1) s += __shfl_xor_sync(~0u, s, o);
    __shared__ int ws[8];
    int lane = t & 31, warp = t >> 5;
    if (lane == 0) ws[warp] = s;
    __syncthreads();
    if (t == 0) {
        int tot = 0;
#pragma unroll
        for (int w = 0; w < 8; w++) tot += ws[w];
        d_blockSums[blockIdx.x] = tot;
    }
}

// ---------------- K2: scans (shuffle based, one block) ---------------------
__global__ void k_scan() {
    int t = threadIdx.x;                 // 1024
    int lane = t & 31, warp = t >> 5;
    __shared__ int ws[32], ws2[8];

    // counts[4096] exclusive scan -> cbase
    int4 c = ((const int4*)d_counts)[t];
    int s = c.x + c.y + c.z + c.w;
    int inc = s;
#pragma unroll
    for (int o = 1; o < 32; o <<= 1) {
        int v = __shfl_up_sync(~0u, inc, o);
        if (lane >= o) inc += v;
    }
    if (lane == 31) ws[warp] = inc;
    __syncthreads();
    if (warp == 0) {
        int v = ws[lane], iv = v;
#pragma unroll
        for (int o = 1; o < 32; o <<= 1) {
            int x = __shfl_up_sync(~0u, iv, o);
            if (lane >= o) iv += x;
        }
        ws[lane] = iv - v;
    }
    __syncthreads();
    int excl = ws[warp] + (inc - s);
    int4 o4;
    o4.x = excl; o4.y = excl + c.x; o4.z = o4.y + c.y; o4.w = o4.z + c.z;
    ((int4*)d_cbase)[t] = o4;
    __syncthreads();

    // blockSums[256] exclusive scan -> blockOff
    int v = 0, inc2 = 0;
    if (t < 256) {
        v = d_blockSums[t];
        inc2 = v;
#pragma unroll
        for (int o = 1; o < 32; o <<= 1) {
            int x = __shfl_up_sync(~0u, inc2, o);
            if (lane >= o) inc2 += x;
        }
        if (lane == 31) ws2[warp] = inc2;
    }
    __syncthreads();
    if (t == 0) {
        int run = 0;
#pragma unroll
        for (int w = 0; w < 8; w++) { int x = ws2[w]; ws2[w] = run; run += x; }
    }
    __syncthreads();
    if (t < 256) d_blockOff[t] = ws2[warp] + (inc2 - v);
}

// ---------------- K3: in-order rank + slot scatter -------------------------
__global__ void k_scatter(const int* __restrict__ mask, const int* __restrict__ batch) {
    int t = threadIdx.x;
    int gid = blockIdx.x * 256 + t;
    int lane = t & 31, warp = t >> 5;
    int4 m = ((const int4*)mask)[gid];
    int4 b = ((const int4*)batch)[gid];
    int g0 = m.x != 0, g1 = m.y != 0, g2 = m.z != 0, g3 = m.w != 0;
    int s = g0 + g1 + g2 + g3;
    int inc = s;
#pragma unroll
    for (int o = 1; o < 32; o <<= 1) {
        int v = __shfl_up_sync(~0u, inc, o);
        if (lane >= o) inc += v;
    }
    __shared__ int ws[8];
    if (lane == 31) ws[warp] = inc;
    __syncthreads();
    if (warp == 0 && lane < 8) {
        int v = ws[lane], iv = v;
#pragma unroll
        for (int o = 1; o < 8; o <<= 1) {
            int x = __shfl_up_sync(0xffu, iv, o);
            if (lane >= o) iv += x;
        }
        ws[lane] = iv - v;
    }
    __syncthreads();
    int pre = d_blockOff[blockIdx.x] + ws[warp] + (inc - s);
    int base = gid * 4;
    if (g0) { int r = pre - d_cbase[b.x]; if (r < GG) d_slotNode[b.x * GG + r] = base;     pre++; }
    if (g1) { int r = pre - d_cbase[b.y]; if (r < GG) d_slotNode[b.y * GG + r] = base + 1; pre++; }
    if (g2) { int r = pre - d_cbase[b.z]; if (r < GG) d_slotNode[b.z * GG + r] = base + 2; pre++; }
    if (g3) { int r = pre - d_cbase[b.w]; if (r < GG) d_slotNode[b.w * GG + r] = base + 3; pre++; }
}

// ---------------- K4: gpart = global @ w1[128:] + b1  (FFMA2) --------------
template <int MR>
__device__ __forceinline__ void mma_loop(const float* __restrict__ Fp,
                                         const float* __restrict__ Wp,
                                         ull_t acc[MR][4]) {
#pragma unroll 1
    for (int k = 0; k < 128; k += 4) {
        float4 fa[MR];
#pragma unroll
        for (int i = 0; i < MR; i++)
            fa[i] = *(const float4*)(Fp + i * 132 + k);
        ull_t wv[4][4];
#pragma unroll
        for (int kk = 0; kk < 4; kk++) {
            const float* wr = Wp + (k + kk) * 128;
#pragma unroll
            for (int jj = 0; jj < 4; jj++)
                wv[kk][jj] = *(const ull_t*)(wr + jj * 2);
        }
#pragma unroll
        for (int kk = 0; kk < 4; kk++) {
#pragma unroll
            for (int i = 0; i < MR; i++) {
                float f = kk == 0 ? fa[i].x : kk == 1 ? fa[i].y
                        : kk == 2 ? fa[i].z : fa[i].w;
                ull_t fp = pack2(f, f);
#pragma unroll
                for (int jj = 0; jj < 4; jj++)
                    acc[i][jj] = fma2(fp, wv[kk][jj], acc[i][jj]);
            }
        }
    }
}

#define GP_SMEM_BYTES ((32 * 132 + 128 * 128 + 128) * 4)
__global__ void k_gpart(const float* __restrict__ gf,
                        const float* __restrict__ w1,
                        const float* __restrict__ b1) {
    extern __shared__ float smem[];
    float* A_s  = smem;
    float* W_s  = smem + 32 * 132;
    float* b1_s = W_s + 128 * 128;

    int t  = threadIdx.x;
    int tx = t & 15, ty = t >> 4;
    int row0 = blockIdx.x * 32;

    {
        const float4* src = (const float4*)(w1 + 128 * 128);
        float4* dst = (float4*)W_s;
        for (int i = t; i < 4096; i += 256) dst[i] = src[i];
    }
    for (int i = t; i < 1024; i += 256) {
        int r = i >> 5, c = i & 31;
        *(float4*)&A_s[r * 132 + c * 4] = ((const float4*)gf)[(row0 + r) * 32 + c];
    }
    if (t < 128) b1_s[t] = b1[t];
    __syncthreads();

    ull_t acc[2][4];
#pragma unroll
    for (int i = 0; i < 2; i++)
#pragma unroll
        for (int j = 0; j < 4; j++) acc[i][j] = 0ull;

    mma_loop<2>(A_s + (ty * 2) * 132, W_s + tx * 8, acc);

#pragma unroll
    for (int i = 0; i < 2; i++) {
        int row = row0 + ty * 2 + i;
#pragma unroll
        for (int jj = 0; jj < 4; jj++) {
            int n = tx * 8 + jj * 2;
            float2 a = unpack2(acc[i][jj]);
            a.x += b1_s[n];
            a.y += b1_s[n + 1];
            *(float2*)&d_gpart[row * 128 + n] = a;
        }
    }
}

// ---------------- K5: main — WMMA bf16 GEMM + fused head -------------------
// 256 blocks x 128 slots, 256 threads (8 warps; warp w owns M-rows 16w..16w+15).
// smem layout (bytes):
//   [0, 69632)   union:  A bf16 [128][136] @0 (34816) + B bf16 [128][136] @34816
//                then H fp32 [128][128] @0 (65536)
//                then Hb bf16 [128][128] @0 (32768)  +  Sc fp32 [128][20] @36864
//   [69632,  77824)  GP fp32 [16][128]
//   [77824,  81920)  W2 bf16 [128][16]
//   [81920,  82432)  nodeS int [128]
#define OFF_B     34816
#define OFF_SC    36864
#define OFF_GP    69632
#define OFF_W2    77824
#define OFF_NODE  81920
#define MAIN_SMEM_BYTES 82432

__global__ void __launch_bounds__(256)
k_main(const float* __restrict__ nf,
       const float* __restrict__ b2,
       const int* __restrict__ mvm,
       float* __restrict__ out) {
    extern __shared__ __align__(16) unsigned char sm[];
    __nv_bfloat16* As   = (__nv_bfloat16*)sm;                 // ldm 136
    __nv_bfloat16* Bs   = (__nv_bfloat16*)(sm + OFF_B);       // ldm 136
    float*         H32  = (float*)sm;                         // ldm 128
    __nv_bfloat16* Hb   = (__nv_bfloat16*)sm;                 // ldm 128
    float*         Sc   = (float*)(sm + OFF_SC);              // ldm 20
    float*         GP   = (float*)(sm + OFF_GP);              // ldm 128
    __nv_bfloat16* W2s  = (__nv_bfloat16*)(sm + OFF_W2);      // ldm 16
    int*           nodeS= (int*)(sm + OFF_NODE);

    int t = threadIdx.x, w = t >> 5;

    if (t < 128) nodeS[t] = d_slotNode[blockIdx.x * 128 + t];
    for (int i = t; i < 2048; i += 256) {          // B: w1 node-half bf16
        int row = i >> 4, c = i & 15;
        *(uint4*)(Bs + row * 136 + c * 8) = ((const uint4*)d_w1bf)[i];
    }
    for (int i = t; i < 512; i += 256)             // gpart tile
        ((float4*)GP)[i] = ((const float4*)(d_gpart + blockIdx.x * 2048))[i];
    if (t < 256 && t < 256)                        // w2 padded bf16 (4096 B)
        ((uint4*)W2s)[t] = ((const uint4*)d_w2b)[t];
    __syncthreads();                               // nodeS ready before gather

    {   // gather node rows -> bf16 A tile (zeros for empty slots)
        const float4* nf4 = (const float4*)nf;
        const float4 z = make_float4(0.f, 0.f, 0.f, 0.f);
        for (int i = t; i < 4096; i += 256) {
            int row = i >> 5, c = i & 31;
            int nd = nodeS[row];
            float4 v = (nd >= 0) ? nf4[nd * 32 + c] : z;
            __nv_bfloat162 p0 = __floats2bfloat162_rn(v.x, v.y);
            __nv_bfloat162 p1 = __floats2bfloat162_rn(v.z, v.w);
            uint2 pk;
            pk.x = *reinterpret_cast<unsigned int*>(&p0);
            pk.y = *reinterpret_cast<unsigned int*>(&p1);
            *(uint2*)(As + row * 136 + c * 4) = pk;
        }
    }
    __syncthreads();

    // ---- layer 1: H = A(128x128) @ B^T? no: H = A @ w1  (B is [k][n]) ----
    wmma::fragment<wmma::matrix_a, 16, 16, 16, __nv_bfloat16, wmma::row_major> fa;
    wmma::fragment<wmma::matrix_b, 16, 16, 16, __nv_bfloat16, wmma::row_major> fb;
    wmma::fragment<wmma::accumulator, 16, 16, 16, float> fc[8];
#pragma unroll
    for (int n = 0; n < 8; n++) wmma::fill_fragment(fc[n], 0.f);

    const __nv_bfloat16* Arow = As + 16 * w * 136;
#pragma unroll
    for (int k = 0; k < 8; k++) {
        wmma::load_matrix_sync(fa, Arow + 16 * k, 136);
#pragma unroll
        for (int n = 0; n < 8; n++) {
            wmma::load_matrix_sync(fb, Bs + 16 * k * 136 + 16 * n, 136);
            wmma::mma_sync(fc[n], fa, fb, fc[n]);
        }
    }
    __syncthreads();                               // A/B dead; write H over them
#pragma unroll
    for (int n = 0; n < 8; n++)
        wmma::store_matrix_sync(H32 + 16 * w * 128 + 16 * n, fc[n], 128,
                                wmma::mem_row_major);
    __syncthreads();

    // ---- relu(H + gpart) -> bf16, in place (read all, sync, write) ----
    {
        int row = t >> 1, half = t & 1;
        const float4* hr = (const float4*)(H32 + row * 128 + half * 64);
        const float4* gr = (const float4*)(GP + (row >> 3) * 128 + half * 64);
        unsigned int pk[32];
#pragma unroll
        for (int j = 0; j < 16; j++) {
            float4 h = hr[j], g = gr[j];
            __nv_bfloat162 p0 = __floats2bfloat162_rn(fmaxf(h.x + g.x, 0.f),
                                                      fmaxf(h.y + g.y, 0.f));
            __nv_bfloat162 p1 = __floats2bfloat162_rn(fmaxf(h.z + g.z, 0.f),
                                                      fmaxf(h.w + g.w, 0.f));
            pk[2 * j]     = *reinterpret_cast<unsigned int*>(&p0);
            pk[2 * j + 1] = *reinterpret_cast<unsigned int*>(&p1);
        }
        __syncthreads();
        uint4* dst = (uint4*)(Hb + row * 128 + half * 64);
#pragma unroll
        for (int j = 0; j < 8; j++)
            dst[j] = make_uint4(pk[4*j], pk[4*j+1], pk[4*j+2], pk[4*j+3]);
    }
    __syncthreads();

    // ---- layer 2: Sc = Hb(128x128) @ W2s(128x16) ----
    {
        wmma::fragment<wmma::matrix_a, 16, 16, 16, __nv_bfloat16, wmma::row_major> fa2;
        wmma::fragment<wmma::matrix_b, 16, 16, 16, __nv_bfloat16, wmma::row_major> fb2;
        wmma::fragment<wmma::accumulator, 16, 16, 16, float> fc2;
        wmma::fill_fragment(fc2, 0.f);
#pragma unroll
        for (int k = 0; k < 8; k++) {
            wmma::load_matrix_sync(fa2, Hb + 16 * w * 128 + 16 * k, 128);
            wmma::load_matrix_sync(fb2, W2s + 16 * k * 16, 16);
            wmma::mma_sync(fc2, fa2, fb2, fc2);
        }
        wmma::store_matrix_sync(Sc + 16 * w * 20, fc2, 20, wmma::mem_row_major);
    }
    __syncthreads();

    // ---- masked output ----
    if (t < 128) {
        int m = t;
        int bb = blockIdx.x * 16 + (m >> 3);
        int orow = bb * (GG * RR) + (m & 7) * RR;
        int occ = nodeS[m] >= 0;
#pragma unroll
        for (int r = 0; r < RR; r++) {
            float v = NEGV;
            if (occ && mvm[orow + r] != 0) v = Sc[m * 20 + r] + b2[r];
            out[orow + r] = v;
        }
    }
}

// ---------------- launch ---------------------------------------------------
extern "C" void kernel_launch(void* const* d_in, const int* in_sizes, int n_in,
                              void* d_out, int out_size) {
    const float* nf    = (const float*)d_in[0];
    const float* gf    = (const float*)d_in[1];
    const int*   gmask = (const int*)d_in[2];
    const int*   mvm   = (const int*)d_in[3];
    const int*   batch = (const int*)d_in[4];
    const float* w1    = (const float*)d_in[5];
    const float* b1    = (const float*)d_in[6];
    const float* w2    = (const float*)d_in[7];
    const float* b2    = (const float*)d_in[8];
    float*       out   = (float*)d_out;

    cudaFuncSetAttribute(k_gpart, cudaFuncAttributeMaxDynamicSharedMemorySize,
                         GP_SMEM_BYTES);
    cudaFuncSetAttribute(k_main, cudaFuncAttributeMaxDynamicSharedMemorySize,
                         MAIN_SMEM_BYTES);

    k_init<<<128, 256>>>(w1, w2);
    k_count<<<256, 256>>>(gmask, batch);
    k_scan<<<1, 1024>>>();
    k_scatter<<<256, 256>>>(gmask, batch);
    k_gpart<<<128, 256, GP_SMEM_BYTES>>>(gf, w1, b1);
    k_main<<<256, 256, MAIN_SMEM_BYTES>>>(nf, b2, mvm, out);
}

// round 5
// speedup vs baseline: 1.8238x; 1.1291x over previous
#include <cuda_runtime.h>
#include <cuda_bf16.h>
#include <mma.h>
#include <cstdint>

// ManeuverHead on GB300 — 2-kernel version.
//  k_front: persistent kernel (grid barriers) = init + block sums + scan +
//           boundary cbase + scatter, weights staged to bf16.
//  k_main : gathered K=256 WMMA bf16 GEMM (node half + global half) + relu
//           + second-layer WMMA + masked output.
// N=262144, B=4096, D=128, G=8, R=7.

#define NNODES   262144
#define NB       4096
#define GG       8
#define RR       7
#define NSLOTS   (NB * GG)
#define NEGV     (-1e9f)
#define FGRID    256

using namespace nvcuda;

// ---------------- device scratch ------------------------------------------
__device__ int            d_blockSums[FGRID];
__device__ int            d_blockOff[FGRID];
__device__ int            d_cbase[NB];
__device__ int            d_slotNode[NSLOTS];
__device__ __nv_bfloat16  d_w1bf[32768];   // full w1 [256][128] bf16
__device__ __nv_bfloat16  d_w2b[2048];     // w2 padded [128][16] bf16
__device__ unsigned int   g_cnt;           // zero-init
__device__ volatile unsigned int g_gen;    // zero-init, monotonically grows

// ---------------- K1: fused front end --------------------------------------
__global__ void __launch_bounds__(256)
k_front(const int* __restrict__ mask, const int* __restrict__ batch,
        const float* __restrict__ w1, const float* __restrict__ w2) {
    int t = threadIdx.x, bid = blockIdx.x;
    int lane = t & 31, warp = t >> 5;
    int gid = bid * 256 + t;

    __shared__ int ws[8];
    __shared__ unsigned int s_gen;
    __shared__ int s_lead;

    // ---- P0: aux init + weight staging (independent work) ----
    if (gid < NSLOTS) d_slotNode[gid] = -1;
    if (gid < 32768)  d_w1bf[gid] = __float2bfloat16(w1[gid]);
    if (gid < 2048) {
        int j = gid >> 4, r = gid & 15;
        d_w2b[gid] = __float2bfloat16(r < RR ? w2[j * RR + r] : 0.f);
    }

    // ---- P0: load 4 elems, block scan of masked flags ----
    int4 m = ((const int4*)mask)[gid];
    int4 b = ((const int4*)batch)[gid];
    int g0 = m.x != 0, g1 = m.y != 0, g2 = m.z != 0, g3 = m.w != 0;
    int s = g0 + g1 + g2 + g3;
    int inc = s;
#pragma unroll
    for (int o = 1; o < 32; o <<= 1) {
        int v = __shfl_up_sync(~0u, inc, o);
        if (lane >= o) inc += v;
    }
    if (lane == 31) ws[warp] = inc;
    __syncthreads();
    if (warp == 0 && lane < 8) {
        int v = ws[lane], iv = v;
#pragma unroll
        for (int o = 1; o < 8; o <<= 1) {
            int x = __shfl_up_sync(0xffu, iv, o);
            if (lane >= o) iv += x;
        }
        ws[lane] = iv - v;                     // exclusive warp prefix
        if (lane == 7) d_blockSums[bid] = iv;  // block total
    }
    __syncthreads();
    int lexcl = ws[warp] + (inc - s);          // block-local excl masked prefix

    // ---- BAR1: leader (last arriver) scans blockSums -> blockOff ----
    __threadfence();
    __syncthreads();
    if (t == 0) {
        s_gen = g_gen;
        unsigned int a = atomicAdd(&g_cnt, 1u);
        s_lead = (a == (unsigned)gridDim.x - 1u);
    }
    __syncthreads();
    if (s_lead) {
        __threadfence();                       // acquire: all blockSums visible
        int v = d_blockSums[t];
        int iv = v;
#pragma unroll
        for (int o = 1; o < 32; o <<= 1) {
            int x = __shfl_up_sync(~0u, iv, o);
            if (lane >= o) iv += x;
        }
        if (lane == 31) ws[warp] = iv;
        __syncthreads();
        if (warp == 0 && lane < 8) {
            int v2 = ws[lane], iv2 = v2;
#pragma unroll
            for (int o = 1; o < 8; o <<= 1) {
                int x = __shfl_up_sync(0xffu, iv2, o);
                if (lane >= o) iv2 += x;
            }
            ws[lane] = iv2 - v2;
        }
        __syncthreads();
        d_blockOff[t] = ws[warp] + (iv - v);
        __threadfence();
        __syncthreads();
        if (t == 0) {
            *(volatile unsigned int*)&g_cnt = 0u;
            __threadfence();
            g_gen = s_gen + 1u;
        }
    } else {
        if (t == 0) {
            while (g_gen == s_gen) __nanosleep(64);
            __threadfence();
        }
        __syncthreads();
    }

    // ---- P2: boundary nodes write cbase[batch] = global masked prefix ----
    int pe0 = d_blockOff[bid] + lexcl;
    int pw = __shfl_up_sync(~0u, b.w, 1);
    int prevb = (lane == 0) ? ((gid > 0) ? batch[gid * 4 - 1] : -1) : pw;
    {
        int pe = pe0;
        if (b.x != prevb) d_cbase[b.x] = pe;  pe += g0;
        if (b.y != b.x)   d_cbase[b.y] = pe;  pe += g1;
        if (b.z != b.y)   d_cbase[b.z] = pe;  pe += g2;
        if (b.w != b.z)   d_cbase[b.w] = pe;
    }

    // ---- BAR2: plain grid barrier ----
    __threadfence();
    __syncthreads();
    if (t == 0) {
        s_gen = g_gen;
        unsigned int a = atomicAdd(&g_cnt, 1u);
        s_lead = (a == (unsigned)gridDim.x - 1u);
    }
    __syncthreads();
    if (s_lead) {
        if (t == 0) {
            *(volatile unsigned int*)&g_cnt = 0u;
            __threadfence();
            g_gen = s_gen + 1u;
        }
        __syncthreads();
    } else {
        if (t == 0) {
            while (g_gen == s_gen) __nanosleep(64);
            __threadfence();
        }
        __syncthreads();
    }

    // ---- P3: scatter ----
    int base = gid * 4;
    int pre = pe0;
    if (g0) { int r = pre - d_cbase[b.x]; if (r < GG) d_slotNode[b.x * GG + r] = base;     pre++; }
    if (g1) { int r = pre - d_cbase[b.y]; if (r < GG) d_slotNode[b.y * GG + r] = base + 1; pre++; }
    if (g2) { int r = pre - d_cbase[b.z]; if (r < GG) d_slotNode[b.z * GG + r] = base + 2; pre++; }
    if (g3) { int r = pre - d_cbase[b.w]; if (r < GG) d_slotNode[b.w * GG + r] = base + 3; }
}

// ---------------- K2: main — K=256 WMMA bf16 GEMM + fused head -------------
// smem (bytes):
//   Bs  bf16 [256][136] @0          (69632)   full w1
//   As  bf16 [128][136] @69632      (34816)   staged A (nodes, then globals)
//   W2s bf16 [128][16]  @104448     (4096)
//   nodeS int [128]     @108544     (512)
//   b1s fp32 [128]      @109056     (512)
//   after MMAs (Bs/As dead):
//   H32 fp32 [128][128] @0 (65536) -> Hb bf16 [128][128] @0 (32768)
//   Sc  fp32 [128][20]  @36864     (10240)
#define OFF_AS    69632
#define OFF_W2    104448
#define OFF_NODE  108544
#define OFF_B1    109056
#define OFF_SC    36864
#define MAIN_SMEM_BYTES 109568

__global__ void __launch_bounds__(256)
k_main(const float* __restrict__ nf,
       const float* __restrict__ gf,
       const float* __restrict__ b1,
       const float* __restrict__ b2,
       const int* __restrict__ mvm,
       float* __restrict__ out) {
    extern __shared__ __align__(16) unsigned char sm[];
    __nv_bfloat16* Bs   = (__nv_bfloat16*)sm;                 // ldm 136
    __nv_bfloat16* As   = (__nv_bfloat16*)(sm + OFF_AS);      // ldm 136
    __nv_bfloat16* W2s  = (__nv_bfloat16*)(sm + OFF_W2);      // ldm 16
    int*           nodeS= (int*)(sm + OFF_NODE);
    float*         b1s  = (float*)(sm + OFF_B1);
    float*         H32  = (float*)sm;                         // ldm 128
    __nv_bfloat16* Hb   = (__nv_bfloat16*)sm;                 // ldm 128
    float*         Sc   = (float*)(sm + OFF_SC);              // ldm 20

    int t = threadIdx.x, w = t >> 5;
    int b0 = blockIdx.x * 16;

    if (t < 128) nodeS[t] = d_slotNode[blockIdx.x * 128 + t];
    for (int i = t; i < 4096; i += 256) {          // full w1 bf16 -> Bs
        int row = i >> 4, c = i & 15;
        *(uint4*)(Bs + row * 136 + c * 8) = ((const uint4*)d_w1bf)[i];
    }
    ((uint4*)W2s)[t] = ((const uint4*)d_w2b)[t];   // 256 uint4 exactly
    if (t < 128) b1s[t] = b1[t];
    __syncthreads();                               // nodeS ready

    {   // stage 1 A: gathered node rows (zeros for empty slots)
        const float4* nf4 = (const float4*)nf;
        const float4 z = make_float4(0.f, 0.f, 0.f, 0.f);
        for (int i = t; i < 4096; i += 256) {
            int row = i >> 5, c = i & 31;
            int nd = nodeS[row];
            float4 v = (nd >= 0) ? nf4[nd * 32 + c] : z;
            __nv_bfloat162 p0 = __floats2bfloat162_rn(v.x, v.y);
            __nv_bfloat162 p1 = __floats2bfloat162_rn(v.z, v.w);
            uint2 pk;
            pk.x = *reinterpret_cast<unsigned int*>(&p0);
            pk.y = *reinterpret_cast<unsigned int*>(&p1);
            *(uint2*)(As + row * 136 + c * 4) = pk;
        }
    }
    __syncthreads();

    wmma::fragment<wmma::matrix_a, 16, 16, 16, __nv_bfloat16, wmma::row_major> fa;
    wmma::fragment<wmma::matrix_b, 16, 16, 16, __nv_bfloat16, wmma::row_major> fb;
    wmma::fragment<wmma::accumulator, 16, 16, 16, float> fc[8];
#pragma unroll
    for (int n = 0; n < 8; n++) wmma::fill_fragment(fc[n], 0.f);

    const __nv_bfloat16* Arow = As + 16 * w * 136;
#pragma unroll
    for (int k = 0; k < 8; k++) {                  // node half (Bs rows 0..127)
        wmma::load_matrix_sync(fa, Arow + 16 * k, 136);
#pragma unroll
        for (int n = 0; n < 8; n++) {
            wmma::load_matrix_sync(fb, Bs + 16 * k * 136 + 16 * n, 136);
            wmma::mma_sync(fc[n], fa, fb, fc[n]);
        }
    }
    __syncthreads();                               // As consumed

    {   // stage 2 A: per-batch global rows broadcast to the batch's 8 slots
        const float4* gf4 = (const float4*)gf;
        for (int i = t; i < 4096; i += 256) {
            int row = i >> 5, c = i & 31;
            float4 v = gf4[(b0 + (row >> 3)) * 32 + c];
            __nv_bfloat162 p0 = __floats2bfloat162_rn(v.x, v.y);
            __nv_bfloat162 p1 = __floats2bfloat162_rn(v.z, v.w);
            uint2 pk;
            pk.x = *reinterpret_cast<unsigned int*>(&p0);
            pk.y = *reinterpret_cast<unsigned int*>(&p1);
            *(uint2*)(As + row * 136 + c * 4) = pk;
        }
    }
    __syncthreads();

#pragma unroll
    for (int k = 0; k < 8; k++) {                  // global half (Bs rows 128..255)
        wmma::load_matrix_sync(fa, Arow + 16 * k, 136);
#pragma unroll
        for (int n = 0; n < 8; n++) {
            wmma::load_matrix_sync(fb, Bs + (128 + 16 * k) * 136 + 16 * n, 136);
            wmma::mma_sync(fc[n], fa, fb, fc[n]);
        }
    }
    __syncthreads();                               // Bs/As dead -> H32 reuses smem
#pragma unroll
    for (int n = 0; n < 8; n++)
        wmma::store_matrix_sync(H32 + 16 * w * 128 + 16 * n, fc[n], 128,
                                wmma::mem_row_major);
    __syncthreads();

    // ---- relu(H + b1) -> bf16, in place ----
    {
        int row = t >> 1, half = t & 1;
        const float4* hr = (const float4*)(H32 + row * 128 + half * 64);
        const float4* br = (const float4*)(b1s + half * 64);
        unsigned int pk[32];
#pragma unroll
        for (int j = 0; j < 16; j++) {
            float4 h = hr[j], g = br[j];
            __nv_bfloat162 p0 = __floats2bfloat162_rn(fmaxf(h.x + g.x, 0.f),
                                                      fmaxf(h.y + g.y, 0.f));
            __nv_bfloat162 p1 = __floats2bfloat162_rn(fmaxf(h.z + g.z, 0.f),
                                                      fmaxf(h.w + g.w, 0.f));
            pk[2 * j]     = *reinterpret_cast<unsigned int*>(&p0);
            pk[2 * j + 1] = *reinterpret_cast<unsigned int*>(&p1);
        }
        __syncthreads();
        uint4* dst = (uint4*)(Hb + row * 128 + half * 64);
#pragma unroll
        for (int j = 0; j < 8; j++)
            dst[j] = make_uint4(pk[4*j], pk[4*j+1], pk[4*j+2], pk[4*j+3]);
    }
    __syncthreads();

    // ---- layer 2: Sc = Hb(128x128) @ W2s(128x16) ----
    {
        wmma::fragment<wmma::matrix_a, 16, 16, 16, __nv_bfloat16, wmma::row_major> fa2;
        wmma::fragment<wmma::matrix_b, 16, 16, 16, __nv_bfloat16, wmma::row_major> fb2;
        wmma::fragment<wmma::accumulator, 16, 16, 16, float> fc2;
        wmma::fill_fragment(fc2, 0.f);
#pragma unroll
        for (int k = 0; k < 8; k++) {
            wmma::load_matrix_sync(fa2, Hb + 16 * w * 128 + 16 * k, 128);
            wmma::load_matrix_sync(fb2, W2s + 16 * k * 16, 16);
            wmma::mma_sync(fc2, fa2, fb2, fc2);
        }
        wmma::store_matrix_sync(Sc + 16 * w * 20, fc2, 20, wmma::mem_row_major);
    }
    __syncthreads();

    // ---- masked output ----
    if (t < 128) {
        int m = t;
        int bb = b0 + (m >> 3);
        int orow = bb * (GG * RR) + (m & 7) * RR;
        int occ = nodeS[m] >= 0;
#pragma unroll
        for (int r = 0; r < RR; r++) {
            float v = NEGV;
            if (occ && mvm[orow + r] != 0) v = Sc[m * 20 + r] + b2[r];
            out[orow + r] = v;
        }
    }
}

// ---------------- launch ---------------------------------------------------
extern "C" void kernel_launch(void* const* d_in, const int* in_sizes, int n_in,
                              void* d_out, int out_size) {
    const float* nf    = (const float*)d_in[0];
    const float* gf    = (const float*)d_in[1];
    const int*   gmask = (const int*)d_in[2];
    const int*   mvm   = (const int*)d_in[3];
    const int*   batch = (const int*)d_in[4];
    const float* w1    = (const float*)d_in[5];
    const float* b1    = (const float*)d_in[6];
    const float* w2    = (const float*)d_in[7];
    const float* b2    = (const float*)d_in[8];
    float*       out   = (float*)d_out;

    cudaFuncSetAttribute(k_main, cudaFuncAttributeMaxDynamicSharedMemorySize,
                         MAIN_SMEM_BYTES);

    k_front<<<FGRID, 256>>>(gmask, batch, w1, w2);
    k_main<<<256, 256, MAIN_SMEM_BYTES>>>(nf, gf, b1, b2, mvm, out);
}